// round 1
// baseline (speedup 1.0000x reference)
#include <cuda_runtime.h>
#include <math.h>

// ---------------- problem constants ----------------
#define IMG      1024
#define FEAT     256          // backbone output spatial
#define CB       128          // backbone channels
#define FM       254          // inter conv output spatial
#define CI       256          // inter conv channels
#define NPOS     (FM*FM)      // 64516 positions
#define N_ANCH   (NPOS*9)     // 580644 anchors
#define K_GT     16

// ---------------- scratch (static device memory; no allocation) ----------------
__device__ float d_feats[FEAT*FEAT*CB];     // 32 MB
__device__ float d_fmap [FM*FM*CI];         // 66 MB
__device__ unsigned int d_gtkey[K_GT];
__device__ double d_acc[4];                 // cls_sum, sel_cnt, box_sum, pos_cnt

// ---------------- helpers ----------------
__device__ __forceinline__ unsigned int fkey(float f) {
    unsigned int u = __float_as_uint(f);
    return (u & 0x80000000u) ? ~u : (u | 0x80000000u);
}
__device__ __forceinline__ float fdecode(unsigned int k) {
    return (k & 0x80000000u) ? __uint_as_float(k & 0x7fffffffu) : __uint_as_float(~k);
}

// IoU with exact, non-contracted fp32 op order (matches the reference formula).
__device__ __forceinline__ float iou_exact(float ax1, float ay1, float ax2, float ay2,
                                           float gx1, float gy1, float gx2, float gy2) {
    const float g = 1.0f / 1024.0f;   // exact in fp32
    float s1 = __fmul_rn(__fadd_rn(__fadd_rn(ax2, -ax1), g),
                         __fadd_rn(__fadd_rn(ay2, -ay1), g));
    float s2 = __fmul_rn(__fadd_rn(__fadd_rn(gx2, -gx1), g),
                         __fadd_rn(__fadd_rn(gy2, -gy1), g));
    float xa = fmaxf(ax1, gx1), ya = fmaxf(ay1, gy1);
    float xb = fminf(ax2, gx2), yb = fminf(ay2, gy2);
    float iw = fmaxf(__fadd_rn(__fadd_rn(xb, -xa), g), 0.0f);
    float ih = fmaxf(__fadd_rn(__fadd_rn(yb, -ya), g), 0.0f);
    float inter = __fmul_rn(iw, ih);
    return __fdiv_rn(inter, __fadd_rn(__fadd_rn(s1, s2), -inter));
}

// anchor box for flat index decomposition (u -> x grid, v -> y grid, a -> ratio/scale)
__device__ __forceinline__ void anchor_box(int u, int v, int a,
                                           float& x1, float& y1, float& x2, float& y2,
                                           bool& inside) {
    const double STEP = 1.0 / 254.0;                 // matches np.arange in f64 then cast
    float cx = (float)((double)u * STEP);
    float cy = (float)((double)v * STEP);
    const float RAT[3] = {0.5f, 1.0f, 2.0f};
    const float SCL[3] = {0.2f, 0.4f, 0.7f};
    int ri = a / 3;
    int si = a - ri * 3;
    float r = sqrtf(RAT[ri]);
    float s = SCL[si];
    float w = __fmul_rn(s, r);
    float h = __fdiv_rn(s, r);
    float hwp = __fmul_rn(w, 0.5f);
    float hhp = __fmul_rn(h, 0.5f);
    float hwn = __fmul_rn(hwp, -1.0f);
    float hhn = __fmul_rn(hhp, -1.0f);
    x1 = __fadd_rn(cx, hwn);
    y1 = __fadd_rn(cy, hhn);
    x2 = __fadd_rn(cx, hwp);
    y2 = __fadd_rn(cy, hhp);
    inside = (x1 >= 0.0f) && (y1 >= 0.0f) && (x2 < 1.0f) && (y2 < 1.0f);
}

__device__ __forceinline__ float softplus_f(float x) {
    return fmaxf(x, 0.0f) + log1pf(expf(-fabsf(x)));
}

// ---------------- kernel 0: init accumulators ----------------
__global__ void init_kernel() {
    int t = threadIdx.x;
    if (t < 4)    d_acc[t] = 0.0;
    if (t < K_GT) d_gtkey[t] = 0u;
}

// ---------------- kernel 1: backbone conv 4x4/s4, 3->128 ----------------
// block = 128 threads (one per out channel), 16 output positions along x per block
__global__ void backbone_kernel(const float* __restrict__ img,
                                const float* __restrict__ Wb,
                                const float* __restrict__ bb) {
    __shared__ __align__(16) float Ws[48 * 128];
    __shared__ __align__(16) float patch[16][48];
    int t   = threadIdx.x;
    int oy  = blockIdx.y;
    int ox0 = blockIdx.x * 16;

    #pragma unroll
    for (int i = 0; i < 48; i++) Ws[t + 128 * i] = Wb[t + 128 * i];

    int oy4 = oy * 4;
    #pragma unroll
    for (int i = 0; i < 6; i++) {
        int idx = t + 128 * i;               // 768 total
        int p = idx / 48, k = idx % 48;
        int ky = k / 12, r12 = k % 12;
        patch[p][k] = img[(oy4 + ky) * 3072 + (ox0 + p) * 12 + r12];
    }
    __syncthreads();

    float wr[48];
    #pragma unroll
    for (int k = 0; k < 48; k++) wr[k] = Ws[k * 128 + t];
    float bias = bb[t];

    #pragma unroll 4
    for (int p = 0; p < 16; p++) {
        float acc = bias;
        const float4* pp = (const float4*)patch[p];
        #pragma unroll
        for (int q = 0; q < 12; q++) {
            float4 v = pp[q];
            acc += v.x * wr[q * 4 + 0];
            acc += v.y * wr[q * 4 + 1];
            acc += v.z * wr[q * 4 + 2];
            acc += v.w * wr[q * 4 + 3];
        }
        d_feats[(oy * FEAT + (ox0 + p)) * CB + t] = acc;
    }
}

// ---------------- kernel 2: inter conv 3x3, 128->256 (implicit GEMM) ----------------
// tile: 128 positions (one row segment) x 64 out channels, BK=16, 256 threads
__global__ void inter_kernel(const float* __restrict__ Wi,
                             const float* __restrict__ bi) {
    __shared__ __align__(16) float As[16][128];
    __shared__ __align__(16) float Bs[16][64];
    int tid = threadIdx.x;
    int tx = tid & 15, ty = tid >> 4;
    int u  = blockIdx.z;          // output row
    int v0 = blockIdx.y * 128;    // output col base
    int n0 = blockIdx.x * 64;     // out-channel base

    float acc[8][4];
    #pragma unroll
    for (int i = 0; i < 8; i++)
        #pragma unroll
        for (int j = 0; j < 4; j++) acc[i][j] = 0.0f;

    for (int kc = 0; kc < 72; kc++) {
        int s  = kc >> 3;                 // 3x3 tap (chunks never cross taps: 128 % 16 == 0)
        int c0 = (kc & 7) << 4;           // channel base within tap
        int dy = s / 3, dx = s - dy * 3;

        const float* fbase = d_feats + (u + dy) * (FEAT * CB);
        #pragma unroll
        for (int r = 0; r < 2; r++) {
            int idx = tid + 256 * r;      // 512 float4 loads
            int m   = idx >> 2;
            int q4  = (idx & 3) << 2;
            int col = v0 + m + dx; if (col > 255) col = 255;   // clamp (tail masked on store)
            float4 v = *(const float4*)(fbase + col * CB + c0 + q4);
            As[q4 + 0][m] = v.x; As[q4 + 1][m] = v.y;
            As[q4 + 2][m] = v.z; As[q4 + 3][m] = v.w;
        }
        {
            int kk = tid >> 4;
            int n4 = (tid & 15) << 2;
            float4 v = *(const float4*)(Wi + (s * 128 + c0 + kk) * CI + n0 + n4);
            *(float4*)&Bs[kk][n4] = v;
        }
        __syncthreads();

        #pragma unroll
        for (int kk = 0; kk < 16; kk++) {
            float4 a0 = *(const float4*)&As[kk][ty * 8];
            float4 a1 = *(const float4*)&As[kk][ty * 8 + 4];
            float4 b  = *(const float4*)&Bs[kk][tx * 4];
            float av[8] = {a0.x, a0.y, a0.z, a0.w, a1.x, a1.y, a1.z, a1.w};
            float bv[4] = {b.x, b.y, b.z, b.w};
            #pragma unroll
            for (int i = 0; i < 8; i++)
                #pragma unroll
                for (int j = 0; j < 4; j++)
                    acc[i][j] += av[i] * bv[j];
        }
        __syncthreads();
    }

    float4 bias = *(const float4*)(bi + n0 + tx * 4);
    #pragma unroll
    for (int i = 0; i < 8; i++) {
        int v = v0 + ty * 8 + i;
        if (v < FM) {
            float4 o;
            o.x = acc[i][0] + bias.x; o.y = acc[i][1] + bias.y;
            o.z = acc[i][2] + bias.z; o.w = acc[i][3] + bias.w;
            *(float4*)(d_fmap + (u * FM + v) * CI + n0 + tx * 4) = o;
        }
    }
}

// ---------------- kernel 3: per-gt max IoU over anchors ----------------
__global__ void pass1_kernel(const float* __restrict__ gt) {
    __shared__ unsigned int skey[K_GT];
    __shared__ float sgt[K_GT * 4];
    int t = threadIdx.x;
    if (t < K_GT)     skey[t] = 0u;
    if (t < K_GT * 4) sgt[t]  = gt[t];
    __syncthreads();

    int n = blockIdx.x * blockDim.x + t;
    float iin[K_GT];
    if (n < N_ANCH) {
        int u = n / (FM * 9);
        int rem = n - u * (FM * 9);
        int v = rem / 9;
        int a = rem - v * 9;
        float x1, y1, x2, y2; bool inside;
        anchor_box(u, v, a, x1, y1, x2, y2, inside);
        #pragma unroll
        for (int g = 0; g < K_GT; g++) {
            float io = iou_exact(x1, y1, x2, y2,
                                 sgt[g * 4 + 0], sgt[g * 4 + 1],
                                 sgt[g * 4 + 2], sgt[g * 4 + 3]);
            iin[g] = inside ? io : -1.0f;
        }
    } else {
        #pragma unroll
        for (int g = 0; g < K_GT; g++) iin[g] = -1.0f;
    }

    int lane = t & 31;
    #pragma unroll
    for (int g = 0; g < K_GT; g++) {
        float m = iin[g];
        #pragma unroll
        for (int off = 16; off > 0; off >>= 1)
            m = fmaxf(m, __shfl_xor_sync(0xffffffffu, m, off));
        if (lane == 0) atomicMax(&skey[g], fkey(m));
    }
    __syncthreads();
    if (t < K_GT) atomicMax(&d_gtkey[t], skey[t]);
}

// ---------------- kernel 4: fused 1x1 heads + labels + losses ----------------
// warp per fmap position; lanes 0..8 = anchors
__global__ void loss_kernel(const float* __restrict__ Wc, const float* __restrict__ bc,
                            const float* __restrict__ Wr, const float* __restrict__ br,
                            const float* __restrict__ gt) {
    __shared__ float Wsm[CI * 45];          // [c][o], o<9 cls else reg
    __shared__ float sgt[K_GT * 4];
    __shared__ float sgtmax[K_GT];
    __shared__ double sacc[4];
    int t = threadIdx.x;

    #pragma unroll
    for (int i = 0; i < 45; i++) {
        int idx = t + 256 * i;              // 11520 = 45*256 exactly
        int c = idx / 45, o = idx - c * 45;
        Wsm[idx] = (o < 9) ? Wc[c * 9 + o] : Wr[c * 36 + (o - 9)];
    }
    if (t < K_GT * 4) sgt[t] = gt[t];
    if (t < K_GT)     sgtmax[t] = fdecode(d_gtkey[t]);
    if (t < 4)        sacc[t] = 0.0;
    __syncthreads();

    int w = t >> 5, lane = t & 31;
    int p = blockIdx.x * 8 + w;

    float myc = 0.0f, mysel = 0.0f, mybox = 0.0f, mypos = 0.0f;

    if (p < NPOS) {
        const float* frow = d_fmap + p * CI;
        float f[8];
        #pragma unroll
        for (int j = 0; j < 8; j++) f[j] = frow[lane + 32 * j];

        float cls_v = 0.0f;
        float regv[4] = {0.0f, 0.0f, 0.0f, 0.0f};

        for (int o = 0; o < 45; o++) {
            float sv = 0.0f;
            #pragma unroll
            for (int j = 0; j < 8; j++) sv += f[j] * Wsm[(lane + 32 * j) * 45 + o];
            #pragma unroll
            for (int off = 16; off > 0; off >>= 1)
                sv += __shfl_xor_sync(0xffffffffu, sv, off);
            if (o == lane) cls_v = sv;                    // lanes 0..8 keep their cls
            if (o >= 9) {
                int rr = o - 9;
                if ((rr >> 2) == lane) regv[rr & 3] = sv; // lanes 0..8 keep their 4 regs
            }
        }

        if (lane < 9) {
            int a = lane;
            cls_v += bc[a];
            #pragma unroll
            for (int d = 0; d < 4; d++) regv[d] += br[a * 4 + d];

            int u = p / FM, v = p - u * FM;               // u -> x-grid, v -> y-grid
            float x1, y1, x2, y2; bool inside;
            anchor_box(u, v, a, x1, y1, x2, y2, inside);

            float maxiou = -1e30f;
            bool best = false;
            #pragma unroll
            for (int g = 0; g < K_GT; g++) {
                float io = iou_exact(x1, y1, x2, y2,
                                     sgt[g * 4 + 0], sgt[g * 4 + 1],
                                     sgt[g * 4 + 2], sgt[g * 4 + 3]);
                if (inside && (io == sgtmax[g])) best = true;
                maxiou = fmaxf(maxiou, io);
            }
            bool pos = inside && (best || (maxiou >= 0.5f));

            if (inside) {
                mysel = 1.0f;
                myc = pos ? softplus_f(-cls_v) : softplus_f(cls_v);
            }
            if (pos) {
                mypos = 1.0f;
                #pragma unroll
                for (int d = 0; d < 4; d++) {
                    float ab = fabsf(regv[d]);
                    mybox += (ab < 1.0f) ? (0.5f * ab * ab) : (ab - 0.5f);
                }
            }
        }
    }

    #pragma unroll
    for (int off = 16; off > 0; off >>= 1) {
        myc   += __shfl_xor_sync(0xffffffffu, myc,   off);
        mysel += __shfl_xor_sync(0xffffffffu, mysel, off);
        mybox += __shfl_xor_sync(0xffffffffu, mybox, off);
        mypos += __shfl_xor_sync(0xffffffffu, mypos, off);
    }
    if (lane == 0) {
        atomicAdd(&sacc[0], (double)myc);
        atomicAdd(&sacc[1], (double)mysel);
        atomicAdd(&sacc[2], (double)mybox);
        atomicAdd(&sacc[3], (double)mypos);
    }
    __syncthreads();
    if (t < 4) atomicAdd(&d_acc[t], sacc[t]);
}

// ---------------- kernel 5: finalize ----------------
__global__ void fin_kernel(float* out) {
    if (threadIdx.x == 0) {
        double cls = d_acc[0] / d_acc[1];
        double box = d_acc[2] / d_acc[3];
        out[0] = (float)(cls + box);
    }
}

// ---------------- launch ----------------
extern "C" void kernel_launch(void* const* d_in, const int* in_sizes, int n_in,
                              void* d_out, int out_size) {
    const float* image = (const float*)d_in[0];
    const float* gt    = (const float*)d_in[1];
    const float* Wb    = (const float*)d_in[2];
    const float* bb    = (const float*)d_in[3];
    const float* Wi    = (const float*)d_in[4];
    const float* bi    = (const float*)d_in[5];
    const float* Wc    = (const float*)d_in[6];
    const float* bc    = (const float*)d_in[7];
    const float* Wr    = (const float*)d_in[8];
    const float* br    = (const float*)d_in[9];

    init_kernel<<<1, 32>>>();
    backbone_kernel<<<dim3(16, 256), 128>>>(image, Wb, bb);
    inter_kernel<<<dim3(4, 2, 254), 256>>>(Wi, bi);
    pass1_kernel<<<(N_ANCH + 255) / 256, 256>>>(gt);
    loss_kernel<<<(NPOS + 7) / 8, 256>>>(Wc, bc, Wr, br, gt);
    fin_kernel<<<1, 32>>>((float*)d_out);
}

// round 3
// speedup vs baseline: 2.8356x; 2.8356x over previous
#include <cuda_runtime.h>
#include <math.h>

// ---------------- problem constants ----------------
#define IMG      1024
#define FEAT     256          // backbone output spatial
#define CB       128          // backbone channels
#define FM       254          // head conv output spatial
#define NHEAD    48           // 45 head outputs (9 cls + 36 reg), padded to 48
#define NPOS     (FM*FM)      // 64516 positions
#define N_ANCH   (NPOS*9)     // 580644 anchors
#define K_GT     16

// ---------------- scratch (static device memory; no allocation) ----------------
__device__ float d_feats[FEAT*FEAT*CB];        // 32 MB
__device__ float d_wfold[9*CB*NHEAD];          // folded 3x3 conv weights 128->45(48)
__device__ float d_bfold[NHEAD];
__device__ float d_head [NPOS*NHEAD];          // 12.4 MB (cls 0..8, reg 9..44)
__device__ unsigned int d_gtkey[K_GT];
__device__ double d_acc[4];                    // cls_sum, sel_cnt, box_sum, pos_cnt

// ---------------- helpers ----------------
__device__ __forceinline__ unsigned int fkey(float f) {
    unsigned int u = __float_as_uint(f);
    return (u & 0x80000000u) ? ~u : (u | 0x80000000u);
}
__device__ __forceinline__ float fdecode(unsigned int k) {
    return (k & 0x80000000u) ? __uint_as_float(k & 0x7fffffffu) : __uint_as_float(~k);
}

// IoU with exact, non-contracted fp32 op order (matches the reference formula).
__device__ __forceinline__ float iou_exact(float ax1, float ay1, float ax2, float ay2,
                                           float gx1, float gy1, float gx2, float gy2) {
    const float g = 1.0f / 1024.0f;   // exact in fp32
    float s1 = __fmul_rn(__fadd_rn(__fadd_rn(ax2, -ax1), g),
                         __fadd_rn(__fadd_rn(ay2, -ay1), g));
    float s2 = __fmul_rn(__fadd_rn(__fadd_rn(gx2, -gx1), g),
                         __fadd_rn(__fadd_rn(gy2, -gy1), g));
    float xa = fmaxf(ax1, gx1), ya = fmaxf(ay1, gy1);
    float xb = fminf(ax2, gx2), yb = fminf(ay2, gy2);
    float iw = fmaxf(__fadd_rn(__fadd_rn(xb, -xa), g), 0.0f);
    float ih = fmaxf(__fadd_rn(__fadd_rn(yb, -ya), g), 0.0f);
    float inter = __fmul_rn(iw, ih);
    return __fdiv_rn(inter, __fadd_rn(__fadd_rn(s1, s2), -inter));
}

// anchor box for flat index decomposition (u -> x grid, v -> y grid, a -> ratio/scale)
__device__ __forceinline__ void anchor_box(int u, int v, int a,
                                           float& x1, float& y1, float& x2, float& y2,
                                           bool& inside) {
    const double STEP = 1.0 / 254.0;
    float cx = (float)((double)u * STEP);
    float cy = (float)((double)v * STEP);
    const float RAT[3] = {0.5f, 1.0f, 2.0f};
    const float SCL[3] = {0.2f, 0.4f, 0.7f};
    int ri = a / 3;
    int si = a - ri * 3;
    float r = sqrtf(RAT[ri]);
    float s = SCL[si];
    float w = __fmul_rn(s, r);
    float h = __fdiv_rn(s, r);
    float hwp = __fmul_rn(w, 0.5f);
    float hhp = __fmul_rn(h, 0.5f);
    float hwn = __fmul_rn(hwp, -1.0f);
    float hhn = __fmul_rn(hhp, -1.0f);
    x1 = __fadd_rn(cx, hwn);
    y1 = __fadd_rn(cy, hhn);
    x2 = __fadd_rn(cx, hwp);
    y2 = __fadd_rn(cy, hhp);
    inside = (x1 >= 0.0f) && (y1 >= 0.0f) && (x2 < 1.0f) && (y2 < 1.0f);
}

__device__ __forceinline__ float softplus_f(float x) {
    return fmaxf(x, 0.0f) + log1pf(expf(-fabsf(x)));
}

// ---------------- kernel 0: init accumulators ----------------
__global__ void init_kernel() {
    int t = threadIdx.x;
    if (t < 4)    d_acc[t] = 0.0;
    if (t < K_GT) d_gtkey[t] = 0u;
}

// ---------------- kernel 1: backbone conv 4x4/s4, 3->128 ----------------
__global__ void backbone_kernel(const float* __restrict__ img,
                                const float* __restrict__ Wb,
                                const float* __restrict__ bb) {
    __shared__ __align__(16) float Ws[48 * 128];
    __shared__ __align__(16) float patch[16][48];
    int t   = threadIdx.x;
    int oy  = blockIdx.y;
    int ox0 = blockIdx.x * 16;

    #pragma unroll
    for (int i = 0; i < 48; i++) Ws[t + 128 * i] = Wb[t + 128 * i];

    int oy4 = oy * 4;
    #pragma unroll
    for (int i = 0; i < 6; i++) {
        int idx = t + 128 * i;               // 768 total
        int p = idx / 48, k = idx % 48;
        int ky = k / 12, r12 = k % 12;
        patch[p][k] = img[(oy4 + ky) * 3072 + (ox0 + p) * 12 + r12];
    }
    __syncthreads();

    float wr[48];
    #pragma unroll
    for (int k = 0; k < 48; k++) wr[k] = Ws[k * 128 + t];
    float bias = bb[t];

    #pragma unroll 4
    for (int p = 0; p < 16; p++) {
        float acc = bias;
        const float4* pp = (const float4*)patch[p];
        #pragma unroll
        for (int q = 0; q < 12; q++) {
            float4 v = pp[q];
            acc += v.x * wr[q * 4 + 0];
            acc += v.y * wr[q * 4 + 1];
            acc += v.z * wr[q * 4 + 2];
            acc += v.w * wr[q * 4 + 3];
        }
        d_feats[(oy * FEAT + (ox0 + p)) * CB + t] = acc;
    }
}

// ---------------- kernel 2a: fold head weights through the 3x3 conv ----------------
// Wf[r][o] = sum_m Wi[r][m] * H[m][o],  r in [0,1152), H = [Wc | Wr] (45 cols)
__global__ void fold_w_kernel(const float* __restrict__ Wi,
                              const float* __restrict__ Wc,
                              const float* __restrict__ Wr) {
    __shared__ float wrow[256];
    int r = blockIdx.x;              // 1152 rows
    int t = threadIdx.x;             // 64 threads
    #pragma unroll
    for (int i = 0; i < 4; i++) wrow[t + 64 * i] = Wi[r * 256 + t + 64 * i];
    __syncthreads();
    if (t < NHEAD) {
        float acc = 0.0f;
        if (t < 45) {
            if (t < 9) {
                for (int m = 0; m < 256; m++) acc += wrow[m] * Wc[m * 9 + t];
            } else {
                int o = t - 9;
                for (int m = 0; m < 256; m++) acc += wrow[m] * Wr[m * 36 + o];
            }
        }
        d_wfold[r * NHEAD + t] = acc;
    }
}

// ---------------- kernel 2b: fold biases ----------------
__global__ void fold_b_kernel(const float* __restrict__ bi,
                              const float* __restrict__ Wc, const float* __restrict__ bc,
                              const float* __restrict__ Wr, const float* __restrict__ br) {
    int t = threadIdx.x;             // 64 threads
    if (t < NHEAD) {
        float acc = 0.0f;
        if (t < 45) {
            if (t < 9) {
                for (int m = 0; m < 256; m++) acc += bi[m] * Wc[m * 9 + t];
                acc += bc[t];
            } else {
                int o = t - 9;
                for (int m = 0; m < 256; m++) acc += bi[m] * Wr[m * 36 + o];
                acc += br[o];
            }
        }
        d_bfold[t] = acc;
    }
}

// ---------------- kernel 3: fused 3x3 conv 128->48 (implicit GEMM) ----------------
// tile: 128 positions (one row segment) x 48 outputs, BK=16, 256 threads (16x16),
// each thread: 8 positions x 3 outputs.
__global__ void head_conv_kernel() {
    __shared__ __align__(16) float As[16][128];
    __shared__ __align__(16) float Bs[16][NHEAD];
    int tid = threadIdx.x;
    int tx = tid & 15, ty = tid >> 4;
    int u  = blockIdx.y;              // output row
    int v0 = blockIdx.x * 128;        // output col base

    float acc[8][3];
    #pragma unroll
    for (int i = 0; i < 8; i++)
        #pragma unroll
        for (int j = 0; j < 3; j++) acc[i][j] = 0.0f;

    for (int kc = 0; kc < 72; kc++) {
        int s  = kc >> 3;                 // 3x3 tap (chunks never cross taps)
        int c0 = (kc & 7) << 4;           // channel base within tap
        int dy = s / 3, dx = s - dy * 3;

        const float* fbase = d_feats + (u + dy) * (FEAT * CB);
        #pragma unroll
        for (int r = 0; r < 2; r++) {
            int idx = tid + 256 * r;      // 512 float4 loads
            int m   = idx >> 2;
            int q4  = (idx & 3) << 2;
            int col = v0 + m + dx; if (col > 255) col = 255;   // only invalid outputs hit clamp
            float4 v = *(const float4*)(fbase + col * CB + c0 + q4);
            As[q4 + 0][m] = v.x; As[q4 + 1][m] = v.y;
            As[q4 + 2][m] = v.z; As[q4 + 3][m] = v.w;
        }
        if (tid < 192) {                  // 16 x 48 = 768 floats = 192 float4
            int kk = tid / 12;
            int n4 = (tid % 12) * 4;
            float4 v = *(const float4*)(d_wfold + (s * 128 + c0 + kk) * NHEAD + n4);
            *(float4*)&Bs[kk][n4] = v;
        }
        __syncthreads();

        #pragma unroll
        for (int kk = 0; kk < 16; kk++) {
            float4 a0 = *(const float4*)&As[kk][ty * 8];
            float4 a1 = *(const float4*)&As[kk][ty * 8 + 4];
            float b0 = Bs[kk][tx * 3 + 0];
            float b1 = Bs[kk][tx * 3 + 1];
            float b2 = Bs[kk][tx * 3 + 2];
            float av[8] = {a0.x, a0.y, a0.z, a0.w, a1.x, a1.y, a1.z, a1.w};
            #pragma unroll
            for (int i = 0; i < 8; i++) {
                acc[i][0] += av[i] * b0;
                acc[i][1] += av[i] * b1;
                acc[i][2] += av[i] * b2;
            }
        }
        __syncthreads();
    }

    float bo0 = d_bfold[tx * 3 + 0];
    float bo1 = d_bfold[tx * 3 + 1];
    float bo2 = d_bfold[tx * 3 + 2];
    #pragma unroll
    for (int i = 0; i < 8; i++) {
        int v = v0 + ty * 8 + i;
        if (v < FM) {
            float* o = d_head + (u * FM + v) * NHEAD + tx * 3;
            o[0] = acc[i][0] + bo0;
            o[1] = acc[i][1] + bo1;
            o[2] = acc[i][2] + bo2;
        }
    }
}

// ---------------- kernel 4: per-gt max IoU over anchors ----------------
__global__ void pass1_kernel(const float* __restrict__ gt) {
    __shared__ unsigned int skey[K_GT];
    __shared__ float sgt[K_GT * 4];
    int t = threadIdx.x;
    if (t < K_GT)     skey[t] = 0u;
    if (t < K_GT * 4) sgt[t]  = gt[t];
    __syncthreads();

    int n = blockIdx.x * blockDim.x + t;
    float iin[K_GT];
    if (n < N_ANCH) {
        int u = n / (FM * 9);
        int rem = n - u * (FM * 9);
        int v = rem / 9;
        int a = rem - v * 9;
        float x1, y1, x2, y2; bool inside;
        anchor_box(u, v, a, x1, y1, x2, y2, inside);
        #pragma unroll
        for (int g = 0; g < K_GT; g++) {
            float io = iou_exact(x1, y1, x2, y2,
                                 sgt[g * 4 + 0], sgt[g * 4 + 1],
                                 sgt[g * 4 + 2], sgt[g * 4 + 3]);
            iin[g] = inside ? io : -1.0f;
        }
    } else {
        #pragma unroll
        for (int g = 0; g < K_GT; g++) iin[g] = -1.0f;
    }

    int lane = t & 31;
    #pragma unroll
    for (int g = 0; g < K_GT; g++) {
        float m = iin[g];
        #pragma unroll
        for (int off = 16; off > 0; off >>= 1)
            m = fmaxf(m, __shfl_xor_sync(0xffffffffu, m, off));
        if (lane == 0) atomicMax(&skey[g], fkey(m));
    }
    __syncthreads();
    if (t < K_GT) atomicMax(&d_gtkey[t], skey[t]);
}

// ---------------- kernel 5: labels + losses (heads precomputed) ----------------
// warp per fmap position; lanes 0..8 = anchors, each lane loads its own 5 head values
__global__ void loss_kernel(const float* __restrict__ gt) {
    __shared__ float sgt[K_GT * 4];
    __shared__ float sgtmax[K_GT];
    __shared__ double sacc[4];
    int t = threadIdx.x;
    if (t < K_GT * 4) sgt[t] = gt[t];
    if (t < K_GT)     sgtmax[t] = fdecode(d_gtkey[t]);
    if (t < 4)        sacc[t] = 0.0;
    __syncthreads();

    int w = t >> 5, lane = t & 31;
    int p = blockIdx.x * 8 + w;

    float myc = 0.0f, mysel = 0.0f, mybox = 0.0f, mypos = 0.0f;

    if (p < NPOS && lane < 9) {
        const float* hrow = d_head + p * NHEAD;
        float cls_v = hrow[lane];
        float regv[4];
        #pragma unroll
        for (int d = 0; d < 4; d++) regv[d] = hrow[9 + lane * 4 + d];

        int u = p / FM, v = p - u * FM;               // u -> x-grid, v -> y-grid
        float x1, y1, x2, y2; bool inside;
        anchor_box(u, v, lane, x1, y1, x2, y2, inside);

        float maxiou = -1e30f;
        bool best = false;
        #pragma unroll
        for (int g = 0; g < K_GT; g++) {
            float io = iou_exact(x1, y1, x2, y2,
                                 sgt[g * 4 + 0], sgt[g * 4 + 1],
                                 sgt[g * 4 + 2], sgt[g * 4 + 3]);
            if (inside && (io == sgtmax[g])) best = true;
            maxiou = fmaxf(maxiou, io);
        }
        bool pos = inside && (best || (maxiou >= 0.5f));

        if (inside) {
            mysel = 1.0f;
            myc = pos ? softplus_f(-cls_v) : softplus_f(cls_v);
        }
        if (pos) {
            mypos = 1.0f;
            #pragma unroll
            for (int d = 0; d < 4; d++) {
                float ab = fabsf(regv[d]);
                mybox += (ab < 1.0f) ? (0.5f * ab * ab) : (ab - 0.5f);
            }
        }
    }

    #pragma unroll
    for (int off = 16; off > 0; off >>= 1) {
        myc   += __shfl_xor_sync(0xffffffffu, myc,   off);
        mysel += __shfl_xor_sync(0xffffffffu, mysel, off);
        mybox += __shfl_xor_sync(0xffffffffu, mybox, off);
        mypos += __shfl_xor_sync(0xffffffffu, mypos, off);
    }
    if (lane == 0) {
        atomicAdd(&sacc[0], (double)myc);
        atomicAdd(&sacc[1], (double)mysel);
        atomicAdd(&sacc[2], (double)mybox);
        atomicAdd(&sacc[3], (double)mypos);
    }
    __syncthreads();
    if (t < 4) atomicAdd(&d_acc[t], sacc[t]);
}

// ---------------- kernel 6: finalize ----------------
__global__ void fin_kernel(float* out) {
    if (threadIdx.x == 0) {
        double cls = d_acc[0] / d_acc[1];
        double box = d_acc[2] / d_acc[3];
        out[0] = (float)(cls + box);
    }
}

// ---------------- launch ----------------
extern "C" void kernel_launch(void* const* d_in, const int* in_sizes, int n_in,
                              void* d_out, int out_size) {
    const float* image = (const float*)d_in[0];
    const float* gt    = (const float*)d_in[1];
    const float* Wb    = (const float*)d_in[2];
    const float* bb    = (const float*)d_in[3];
    const float* Wi    = (const float*)d_in[4];
    const float* bi    = (const float*)d_in[5];
    const float* Wc    = (const float*)d_in[6];
    const float* bc    = (const float*)d_in[7];
    const float* Wr    = (const float*)d_in[8];
    const float* br    = (const float*)d_in[9];

    init_kernel<<<1, 32>>>();
    fold_w_kernel<<<1152, 64>>>(Wi, Wc, Wr);
    fold_b_kernel<<<1, 64>>>(bi, Wc, bc, Wr, br);
    backbone_kernel<<<dim3(16, 256), 128>>>(image, Wb, bb);
    head_conv_kernel<<<dim3(2, 254), 256>>>();
    pass1_kernel<<<(N_ANCH + 255) / 256, 256>>>(gt);
    loss_kernel<<<(NPOS + 7) / 8, 256>>>(gt);
    fin_kernel<<<1, 32>>>((float*)d_out);
}

// round 4
// speedup vs baseline: 4.6020x; 1.6230x over previous
#include <cuda_runtime.h>
#include <math.h>
#include <stdint.h>

// ---------------- problem constants ----------------
#define IMG      1024
#define FEAT     256          // backbone output spatial
#define CB       128          // backbone channels
#define FM       254          // head conv output spatial
#define NHEAD    48           // 45 head outputs (9 cls + 36 reg), padded to 48
#define NPOS     (FM*FM)      // 64516 positions
#define N_ANCH   (NPOS*9)     // 580644 anchors
#define K_GT     16

// ---------------- scratch (static device memory; no allocation) ----------------
__device__ float d_feats[FEAT*FEAT*CB];        // 32 MB (tf32-rounded values)
__device__ float d_wf_hi[9*CB*NHEAD];          // folded weights, tf32 hi part
__device__ float d_wf_lo[9*CB*NHEAD];          // folded weights, tf32 lo part
__device__ float d_bfold[NHEAD];
__device__ float d_head [NPOS*NHEAD];          // 12.4 MB (cls 0..8, reg 9..44)
__device__ unsigned int d_gtkey[K_GT];
__device__ double d_acc[4];                    // cls_sum, sel_cnt, box_sum, pos_cnt

// ---------------- helpers ----------------
__device__ __forceinline__ unsigned int fkey(float f) {
    unsigned int u = __float_as_uint(f);
    return (u & 0x80000000u) ? ~u : (u | 0x80000000u);
}
__device__ __forceinline__ float fdecode(unsigned int k) {
    return (k & 0x80000000u) ? __uint_as_float(k & 0x7fffffffu) : __uint_as_float(~k);
}
__device__ __forceinline__ float to_tf32(float x) {
    uint32_t r;
    asm("cvt.rna.tf32.f32 %0, %1;" : "=r"(r) : "f"(x));
    return __uint_as_float(r);
}

// IoU with exact, non-contracted fp32 op order (matches the reference formula).
__device__ __forceinline__ float iou_exact(float ax1, float ay1, float ax2, float ay2,
                                           float gx1, float gy1, float gx2, float gy2) {
    const float g = 1.0f / 1024.0f;   // exact in fp32
    float s1 = __fmul_rn(__fadd_rn(__fadd_rn(ax2, -ax1), g),
                         __fadd_rn(__fadd_rn(ay2, -ay1), g));
    float s2 = __fmul_rn(__fadd_rn(__fadd_rn(gx2, -gx1), g),
                         __fadd_rn(__fadd_rn(gy2, -gy1), g));
    float xa = fmaxf(ax1, gx1), ya = fmaxf(ay1, gy1);
    float xb = fminf(ax2, gx2), yb = fminf(ay2, gy2);
    float iw = fmaxf(__fadd_rn(__fadd_rn(xb, -xa), g), 0.0f);
    float ih = fmaxf(__fadd_rn(__fadd_rn(yb, -ya), g), 0.0f);
    float inter = __fmul_rn(iw, ih);
    return __fdiv_rn(inter, __fadd_rn(__fadd_rn(s1, s2), -inter));
}

// anchor box for flat index decomposition (u -> x grid, v -> y grid, a -> ratio/scale)
__device__ __forceinline__ void anchor_box(int u, int v, int a,
                                           float& x1, float& y1, float& x2, float& y2,
                                           bool& inside) {
    const double STEP = 1.0 / 254.0;
    float cx = (float)((double)u * STEP);
    float cy = (float)((double)v * STEP);
    const float RAT[3] = {0.5f, 1.0f, 2.0f};
    const float SCL[3] = {0.2f, 0.4f, 0.7f};
    int ri = a / 3;
    int si = a - ri * 3;
    float r = sqrtf(RAT[ri]);
    float s = SCL[si];
    float w = __fmul_rn(s, r);
    float h = __fdiv_rn(s, r);
    float hwp = __fmul_rn(w, 0.5f);
    float hhp = __fmul_rn(h, 0.5f);
    float hwn = __fmul_rn(hwp, -1.0f);
    float hhn = __fmul_rn(hhp, -1.0f);
    x1 = __fadd_rn(cx, hwn);
    y1 = __fadd_rn(cy, hhn);
    x2 = __fadd_rn(cx, hwp);
    y2 = __fadd_rn(cy, hhp);
    inside = (x1 >= 0.0f) && (y1 >= 0.0f) && (x2 < 1.0f) && (y2 < 1.0f);
}

__device__ __forceinline__ float softplus_f(float x) {
    return fmaxf(x, 0.0f) + log1pf(expf(-fabsf(x)));
}

__device__ __forceinline__ void mma_tf32(float* acc,
                                         uint32_t a0, uint32_t a1, uint32_t a2, uint32_t a3,
                                         uint32_t b0, uint32_t b1) {
    asm volatile("mma.sync.aligned.m16n8k8.row.col.f32.tf32.tf32.f32 "
                 "{%0,%1,%2,%3}, {%4,%5,%6,%7}, {%8,%9}, {%0,%1,%2,%3};"
                 : "+f"(acc[0]), "+f"(acc[1]), "+f"(acc[2]), "+f"(acc[3])
                 : "r"(a0), "r"(a1), "r"(a2), "r"(a3), "r"(b0), "r"(b1));
}

// ---------------- kernel 0: init accumulators ----------------
__global__ void init_kernel() {
    int t = threadIdx.x;
    if (t < 4)    d_acc[t] = 0.0;
    if (t < K_GT) d_gtkey[t] = 0u;
}

// ---------------- kernel 1: backbone conv 4x4/s4, 3->128 (stores tf32-rounded) ----------------
__global__ void backbone_kernel(const float* __restrict__ img,
                                const float* __restrict__ Wb,
                                const float* __restrict__ bb) {
    __shared__ __align__(16) float Ws[48 * 128];
    __shared__ __align__(16) float patch[16][48];
    int t   = threadIdx.x;
    int oy  = blockIdx.y;
    int ox0 = blockIdx.x * 16;

    #pragma unroll
    for (int i = 0; i < 48; i++) Ws[t + 128 * i] = Wb[t + 128 * i];

    int oy4 = oy * 4;
    #pragma unroll
    for (int i = 0; i < 6; i++) {
        int idx = t + 128 * i;               // 768 total
        int p = idx / 48, k = idx % 48;
        int ky = k / 12, r12 = k % 12;
        patch[p][k] = img[(oy4 + ky) * 3072 + (ox0 + p) * 12 + r12];
    }
    __syncthreads();

    float wr[48];
    #pragma unroll
    for (int k = 0; k < 48; k++) wr[k] = Ws[k * 128 + t];
    float bias = bb[t];

    #pragma unroll 4
    for (int p = 0; p < 16; p++) {
        float acc = bias;
        const float4* pp = (const float4*)patch[p];
        #pragma unroll
        for (int q = 0; q < 12; q++) {
            float4 v = pp[q];
            acc += v.x * wr[q * 4 + 0];
            acc += v.y * wr[q * 4 + 1];
            acc += v.z * wr[q * 4 + 2];
            acc += v.w * wr[q * 4 + 3];
        }
        d_feats[(oy * FEAT + (ox0 + p)) * CB + t] = to_tf32(acc);
    }
}

// ---------------- kernel 2a: fold head weights through the 3x3 conv ----------------
// Wf[r][o] = sum_m Wi[r][m] * H[m][o], split into tf32 hi/lo pair.
__global__ void fold_w_kernel(const float* __restrict__ Wi,
                              const float* __restrict__ Wc,
                              const float* __restrict__ Wr) {
    __shared__ float wrow[256];
    int r = blockIdx.x;              // 1152 rows
    int t = threadIdx.x;             // 64 threads
    #pragma unroll
    for (int i = 0; i < 4; i++) wrow[t + 64 * i] = Wi[r * 256 + t + 64 * i];
    __syncthreads();
    if (t < NHEAD) {
        float acc = 0.0f;
        if (t < 45) {
            if (t < 9) {
                for (int m = 0; m < 256; m++) acc += wrow[m] * Wc[m * 9 + t];
            } else {
                int o = t - 9;
                for (int m = 0; m < 256; m++) acc += wrow[m] * Wr[m * 36 + o];
            }
        }
        float hi = to_tf32(acc);
        float lo = to_tf32(acc - hi);
        d_wf_hi[r * NHEAD + t] = hi;
        d_wf_lo[r * NHEAD + t] = lo;
    }
}

// ---------------- kernel 2b: fold biases ----------------
__global__ void fold_b_kernel(const float* __restrict__ bi,
                              const float* __restrict__ Wc, const float* __restrict__ bc,
                              const float* __restrict__ Wr, const float* __restrict__ br) {
    int t = threadIdx.x;             // 64 threads
    if (t < NHEAD) {
        float acc = 0.0f;
        if (t < 45) {
            if (t < 9) {
                for (int m = 0; m < 256; m++) acc += bi[m] * Wc[m * 9 + t];
                acc += bc[t];
            } else {
                int o = t - 9;
                for (int m = 0; m < 256; m++) acc += bi[m] * Wr[m * 36 + o];
                acc += br[o];
            }
        }
        d_bfold[t] = acc;
    }
}

// ---------------- kernel 3: head conv 3x3 128->48 via tf32 tensor-core MMA ----------------
// One block per output row u. 256 positions (254 valid) x 48 outputs.
// mma m16n8k8: M = outputs (3 tiles), N = positions (8 warps x 4 tiles of 8), K = 1152.
// Weights as hi+lo tf32 pair (fp32-accurate); activations single tf32 (pre-rounded).
#define ASTR 20    // smem row stride (words) -> conflict-free fragment access
__global__ __launch_bounds__(256) void head_mma_kernel() {
    __shared__ float As[2][NHEAD * ASTR];      // [hi/lo][o*ASTR + k], k<16
    __shared__ float Bs[256 * ASTR];           // [m*ASTR + k]
    int tid  = threadIdx.x;
    int u    = blockIdx.x;
    int warp = tid >> 5, lane = tid & 31;
    int g = lane >> 2, q = lane & 3;

    float acc[3][4][4];
    #pragma unroll
    for (int mt = 0; mt < 3; mt++)
        #pragma unroll
        for (int nt = 0; nt < 4; nt++)
            #pragma unroll
            for (int i = 0; i < 4; i++) acc[mt][nt][i] = 0.0f;

    for (int kc = 0; kc < 72; kc++) {
        int s  = kc >> 3;                 // 3x3 tap
        int c0 = (kc & 7) << 4;           // channel base within tap (16 per chunk)
        int dy = s / 3, dx = s - dy * 3;
        int base = s * CB + c0;

        __syncthreads();
        // load folded weights (48 outs x 16 k x 2 parts)
        #pragma unroll
        for (int j = 0; j < 3; j++) {
            int idx = tid + 256 * j;      // 0..767
            int k = idx / NHEAD, o = idx - (idx / NHEAD) * NHEAD;
            As[0][o * ASTR + k] = d_wf_hi[(base + k) * NHEAD + o];
            As[1][o * ASTR + k] = d_wf_lo[(base + k) * NHEAD + o];
        }
        // load activations (256 positions x 16 channels)
        const float* fb = d_feats + (u + dy) * (FEAT * CB);
        #pragma unroll
        for (int j = 0; j < 4; j++) {
            int idx = tid + 256 * j;      // 1024 float4
            int m = idx >> 2, qq = idx & 3;
            int col = m + dx; if (col > 255) col = 255;   // only padded outputs touch clamp
            float4 v = *(const float4*)(fb + col * CB + c0 + qq * 4);
            *(float4*)&Bs[m * ASTR + qq * 4] = v;
        }
        __syncthreads();

        #pragma unroll
        for (int ks = 0; ks < 2; ks++) {
            uint32_t bf[4][2];
            #pragma unroll
            for (int nt = 0; nt < 4; nt++) {
                int m = warp * 32 + nt * 8 + g;
                bf[nt][0] = __float_as_uint(Bs[m * ASTR + ks * 8 + q]);
                bf[nt][1] = __float_as_uint(Bs[m * ASTR + ks * 8 + q + 4]);
            }
            #pragma unroll
            for (int mt = 0; mt < 3; mt++) {
                #pragma unroll
                for (int h = 0; h < 2; h++) {
                    int ro = mt * 16;
                    uint32_t a0 = __float_as_uint(As[h][(ro + g    ) * ASTR + ks * 8 + q    ]);
                    uint32_t a1 = __float_as_uint(As[h][(ro + g + 8) * ASTR + ks * 8 + q    ]);
                    uint32_t a2 = __float_as_uint(As[h][(ro + g    ) * ASTR + ks * 8 + q + 4]);
                    uint32_t a3 = __float_as_uint(As[h][(ro + g + 8) * ASTR + ks * 8 + q + 4]);
                    #pragma unroll
                    for (int nt = 0; nt < 4; nt++)
                        mma_tf32(acc[mt][nt], a0, a1, a2, a3, bf[nt][0], bf[nt][1]);
                }
            }
        }
    }

    // epilogue: D[row=out (g,+8), col=pos (2q,2q+1)] per tile
    #pragma unroll
    for (int mt = 0; mt < 3; mt++) {
        float b0 = d_bfold[mt * 16 + g];
        float b1 = d_bfold[mt * 16 + g + 8];
        #pragma unroll
        for (int nt = 0; nt < 4; nt++) {
            int v0 = warp * 32 + nt * 8 + 2 * q;
            #pragma unroll
            for (int c = 0; c < 2; c++) {
                int v = v0 + c;
                if (v < FM) {
                    float* o = d_head + (u * FM + v) * NHEAD + mt * 16 + g;
                    o[0] = acc[mt][nt][0 + c] + b0;
                    o[8] = acc[mt][nt][2 + c] + b1;
                }
            }
        }
    }
}

// ---------------- kernel 4: per-gt max IoU over anchors ----------------
__global__ void pass1_kernel(const float* __restrict__ gt) {
    __shared__ unsigned int skey[K_GT];
    __shared__ float sgt[K_GT * 4];
    int t = threadIdx.x;
    if (t < K_GT)     skey[t] = 0u;
    if (t < K_GT * 4) sgt[t]  = gt[t];
    __syncthreads();

    int n = blockIdx.x * blockDim.x + t;
    float iin[K_GT];
    if (n < N_ANCH) {
        int u = n / (FM * 9);
        int rem = n - u * (FM * 9);
        int v = rem / 9;
        int a = rem - v * 9;
        float x1, y1, x2, y2; bool inside;
        anchor_box(u, v, a, x1, y1, x2, y2, inside);
        #pragma unroll
        for (int g = 0; g < K_GT; g++) {
            float io = iou_exact(x1, y1, x2, y2,
                                 sgt[g * 4 + 0], sgt[g * 4 + 1],
                                 sgt[g * 4 + 2], sgt[g * 4 + 3]);
            iin[g] = inside ? io : -1.0f;
        }
    } else {
        #pragma unroll
        for (int g = 0; g < K_GT; g++) iin[g] = -1.0f;
    }

    int lane = t & 31;
    #pragma unroll
    for (int g = 0; g < K_GT; g++) {
        float m = iin[g];
        #pragma unroll
        for (int off = 16; off > 0; off >>= 1)
            m = fmaxf(m, __shfl_xor_sync(0xffffffffu, m, off));
        if (lane == 0) atomicMax(&skey[g], fkey(m));
    }
    __syncthreads();
    if (t < K_GT) atomicMax(&d_gtkey[t], skey[t]);
}

// ---------------- kernel 5: labels + losses (2 positions per warp) ----------------
__global__ void loss_kernel(const float* __restrict__ gt) {
    __shared__ float sgt[K_GT * 4];
    __shared__ float sgtmax[K_GT];
    __shared__ double sacc[4];
    int t = threadIdx.x;
    if (t < K_GT * 4) sgt[t] = gt[t];
    if (t < K_GT)     sgtmax[t] = fdecode(d_gtkey[t]);
    if (t < 4)        sacc[t] = 0.0;
    __syncthreads();

    int w = t >> 5, lane = t & 31;
    int half = lane >> 4, sub = lane & 15;
    int p = blockIdx.x * 16 + w * 2 + half;

    float myc = 0.0f, mysel = 0.0f, mybox = 0.0f, mypos = 0.0f;

    if (p < NPOS && sub < 9) {
        const float* hrow = d_head + p * NHEAD;
        float cls_v = hrow[sub];
        float regv[4];
        #pragma unroll
        for (int d = 0; d < 4; d++) regv[d] = hrow[9 + sub * 4 + d];

        int u = p / FM, v = p - u * FM;               // u -> x-grid, v -> y-grid
        float x1, y1, x2, y2; bool inside;
        anchor_box(u, v, sub, x1, y1, x2, y2, inside);

        float maxiou = -1e30f;
        bool best = false;
        #pragma unroll
        for (int g = 0; g < K_GT; g++) {
            float io = iou_exact(x1, y1, x2, y2,
                                 sgt[g * 4 + 0], sgt[g * 4 + 1],
                                 sgt[g * 4 + 2], sgt[g * 4 + 3]);
            if (inside && (io == sgtmax[g])) best = true;
            maxiou = fmaxf(maxiou, io);
        }
        bool pos = inside && (best || (maxiou >= 0.5f));

        if (inside) {
            mysel = 1.0f;
            myc = pos ? softplus_f(-cls_v) : softplus_f(cls_v);
        }
        if (pos) {
            mypos = 1.0f;
            #pragma unroll
            for (int d = 0; d < 4; d++) {
                float ab = fabsf(regv[d]);
                mybox += (ab < 1.0f) ? (0.5f * ab * ab) : (ab - 0.5f);
            }
        }
    }

    #pragma unroll
    for (int off = 16; off > 0; off >>= 1) {
        myc   += __shfl_xor_sync(0xffffffffu, myc,   off);
        mysel += __shfl_xor_sync(0xffffffffu, mysel, off);
        mybox += __shfl_xor_sync(0xffffffffu, mybox, off);
        mypos += __shfl_xor_sync(0xffffffffu, mypos, off);
    }
    if (lane == 0) {
        atomicAdd(&sacc[0], (double)myc);
        atomicAdd(&sacc[1], (double)mysel);
        atomicAdd(&sacc[2], (double)mybox);
        atomicAdd(&sacc[3], (double)mypos);
    }
    __syncthreads();
    if (t < 4) atomicAdd(&d_acc[t], sacc[t]);
}

// ---------------- kernel 6: finalize ----------------
__global__ void fin_kernel(float* out) {
    if (threadIdx.x == 0) {
        double cls = d_acc[0] / d_acc[1];
        double box = d_acc[2] / d_acc[3];
        out[0] = (float)(cls + box);
    }
}

// ---------------- launch ----------------
extern "C" void kernel_launch(void* const* d_in, const int* in_sizes, int n_in,
                              void* d_out, int out_size) {
    const float* image = (const float*)d_in[0];
    const float* gt    = (const float*)d_in[1];
    const float* Wb    = (const float*)d_in[2];
    const float* bb    = (const float*)d_in[3];
    const float* Wi    = (const float*)d_in[4];
    const float* bi    = (const float*)d_in[5];
    const float* Wc    = (const float*)d_in[6];
    const float* bc    = (const float*)d_in[7];
    const float* Wr    = (const float*)d_in[8];
    const float* br    = (const float*)d_in[9];

    init_kernel<<<1, 32>>>();
    fold_w_kernel<<<1152, 64>>>(Wi, Wc, Wr);
    fold_b_kernel<<<1, 64>>>(bi, Wc, bc, Wr, br);
    backbone_kernel<<<dim3(16, 256), 128>>>(image, Wb, bb);
    head_mma_kernel<<<FM, 256>>>();
    pass1_kernel<<<(N_ANCH + 255) / 256, 256>>>(gt);
    loss_kernel<<<(NPOS + 15) / 16, 256>>>(gt);
    fin_kernel<<<1, 32>>>((float*)d_out);
}

// round 5
// speedup vs baseline: 5.4270x; 1.1793x over previous
#include <cuda_runtime.h>
#include <math.h>
#include <stdint.h>

// ---------------- problem constants ----------------
#define IMG      1024
#define FEAT     256          // backbone output spatial
#define CB       128          // backbone channels
#define FM       254          // head conv output spatial
#define NHEAD    48           // 45 head outputs (9 cls + 36 reg), padded to 48
#define NPOS     (FM*FM)      // 64516 positions
#define N_ANCH   (NPOS*9)     // 580644 anchors
#define K_GT     16

// ---------------- scratch (static device memory; no allocation) ----------------
__device__ float d_feats[FEAT*FEAT*CB];        // 32 MB (tf32-rounded values)
__device__ float d_wf   [9*CB*NHEAD];          // folded head weights (tf32)
__device__ float d_wbh  [CB*48];               // backbone weights [o][k] tf32 hi
__device__ float d_wbl  [CB*48];               // backbone weights [o][k] tf32 lo
__device__ float d_bfold[NHEAD];
__device__ float d_head [NPOS*NHEAD];          // 12.4 MB (cls 0..8, reg 9..44)
__device__ unsigned int d_gtkey[K_GT];
__device__ double d_acc[4];                    // cls_sum, sel_cnt, box_sum, pos_cnt

// ---------------- helpers ----------------
__device__ __forceinline__ unsigned int fkey(float f) {
    unsigned int u = __float_as_uint(f);
    return (u & 0x80000000u) ? ~u : (u | 0x80000000u);
}
__device__ __forceinline__ float fdecode(unsigned int k) {
    return (k & 0x80000000u) ? __uint_as_float(k & 0x7fffffffu) : __uint_as_float(~k);
}
__device__ __forceinline__ float to_tf32(float x) {
    uint32_t r;
    asm("cvt.rna.tf32.f32 %0, %1;" : "=r"(r) : "f"(x));
    return __uint_as_float(r);
}

// IoU with exact, non-contracted fp32 op order (matches the reference formula).
__device__ __forceinline__ float iou_exact(float ax1, float ay1, float ax2, float ay2,
                                           float gx1, float gy1, float gx2, float gy2) {
    const float g = 1.0f / 1024.0f;   // exact in fp32
    float s1 = __fmul_rn(__fadd_rn(__fadd_rn(ax2, -ax1), g),
                         __fadd_rn(__fadd_rn(ay2, -ay1), g));
    float s2 = __fmul_rn(__fadd_rn(__fadd_rn(gx2, -gx1), g),
                         __fadd_rn(__fadd_rn(gy2, -gy1), g));
    float xa = fmaxf(ax1, gx1), ya = fmaxf(ay1, gy1);
    float xb = fminf(ax2, gx2), yb = fminf(ay2, gy2);
    float iw = fmaxf(__fadd_rn(__fadd_rn(xb, -xa), g), 0.0f);
    float ih = fmaxf(__fadd_rn(__fadd_rn(yb, -ya), g), 0.0f);
    float inter = __fmul_rn(iw, ih);
    return __fdiv_rn(inter, __fadd_rn(__fadd_rn(s1, s2), -inter));
}

// anchor box for flat index decomposition (u -> x grid, v -> y grid, a -> ratio/scale)
__device__ __forceinline__ void anchor_box(int u, int v, int a,
                                           float& x1, float& y1, float& x2, float& y2,
                                           bool& inside) {
    const double STEP = 1.0 / 254.0;
    float cx = (float)((double)u * STEP);
    float cy = (float)((double)v * STEP);
    const float RAT[3] = {0.5f, 1.0f, 2.0f};
    const float SCL[3] = {0.2f, 0.4f, 0.7f};
    int ri = a / 3;
    int si = a - ri * 3;
    float r = sqrtf(RAT[ri]);
    float s = SCL[si];
    float w = __fmul_rn(s, r);
    float h = __fdiv_rn(s, r);
    float hwp = __fmul_rn(w, 0.5f);
    float hhp = __fmul_rn(h, 0.5f);
    float hwn = __fmul_rn(hwp, -1.0f);
    float hhn = __fmul_rn(hhp, -1.0f);
    x1 = __fadd_rn(cx, hwn);
    y1 = __fadd_rn(cy, hhn);
    x2 = __fadd_rn(cx, hwp);
    y2 = __fadd_rn(cy, hhp);
    inside = (x1 >= 0.0f) && (y1 >= 0.0f) && (x2 < 1.0f) && (y2 < 1.0f);
}

__device__ __forceinline__ float softplus_f(float x) {
    return fmaxf(x, 0.0f) + log1pf(expf(-fabsf(x)));
}

__device__ __forceinline__ void mma_tf32(float* acc,
                                         uint32_t a0, uint32_t a1, uint32_t a2, uint32_t a3,
                                         uint32_t b0, uint32_t b1) {
    asm volatile("mma.sync.aligned.m16n8k8.row.col.f32.tf32.tf32.f32 "
                 "{%0,%1,%2,%3}, {%4,%5,%6,%7}, {%8,%9}, {%0,%1,%2,%3};"
                 : "+f"(acc[0]), "+f"(acc[1]), "+f"(acc[2]), "+f"(acc[3])
                 : "r"(a0), "r"(a1), "r"(a2), "r"(a3), "r"(b0), "r"(b1));
}

// ---------------- kernel 0: init ----------------
__global__ void init_kernel() {
    int t = threadIdx.x;
    if (t < 4)    d_acc[t] = 0.0;
    if (t < K_GT) d_gtkey[t] = 0u;
}

// ---------------- kernel 1: backbone weight prep (transpose + tf32 hi/lo) ----------------
// Wb layout in memory: [k][o] with k = ky*12 + px*3 + c (HWIO flattened), o<128.
__global__ void wb_prep_kernel(const float* __restrict__ Wb) {
    int i = blockIdx.x * 256 + threadIdx.x;     // 6144 = 48*128
    if (i < 6144) {
        int o = i / 48, k = i - (i / 48) * 48;
        float w = Wb[k * CB + o];
        float hi = to_tf32(w);
        d_wbh[i] = hi;
        d_wbl[i] = to_tf32(w - hi);
    }
}

// ---------------- kernel 2: backbone conv as tf32 MMA GEMM ----------------
// Non-overlapping 4x4/s4 patches -> pure GEMM: M=128 out-ch, N=65536 pos, K=48.
// Block: 128 positions x 128 channels. Weights hi/lo (exact), acts single tf32.
#define BKS 52
extern __shared__ float bsmem[];
__global__ __launch_bounds__(256) void backbone_mma_kernel(const float* __restrict__ img,
                                                           const float* __restrict__ bbias) {
    float* Wh = bsmem;               // [2][128][BKS]
    float* Bs = bsmem + 2 * CB * BKS;    // [128][BKS]
    float* sb = bsmem + 3 * CB * BKS;    // [128]
    int tid = threadIdx.x;
    int b   = blockIdx.x;
    int oy  = b >> 1;
    int ox0 = (b & 1) * 128;

    #pragma unroll
    for (int i = tid; i < 6144; i += 256) {
        int o = i / 48, k = i - (i / 48) * 48;
        Wh[o * BKS + k]            = d_wbh[i];
        Wh[CB * BKS + o * BKS + k] = d_wbl[i];
    }
    if (tid < 128) sb[tid] = bbias[tid];

    int oy4 = oy * 4;
    #pragma unroll
    for (int i = tid; i < 1536; i += 256) {
        int p = i / 12, j = i - (i / 12) * 12;
        const float* src = img + (oy4 + j / 3) * 3072 + (ox0 + p) * 12 + (j % 3) * 4;
        float4 v = *(const float4*)src;
        float* dst = &Bs[p * BKS + j * 4];
        dst[0] = to_tf32(v.x); dst[1] = to_tf32(v.y);
        dst[2] = to_tf32(v.z); dst[3] = to_tf32(v.w);
    }
    __syncthreads();

    int warp = tid >> 5, lane = tid & 31;
    int g = lane >> 2, q = lane & 3;

    float acc[8][2][4];
    #pragma unroll
    for (int mt = 0; mt < 8; mt++)
        #pragma unroll
        for (int nt = 0; nt < 2; nt++)
            #pragma unroll
            for (int i = 0; i < 4; i++) acc[mt][nt][i] = 0.0f;

    #pragma unroll
    for (int ks = 0; ks < 6; ks++) {
        uint32_t bf[2][2];
        #pragma unroll
        for (int nt = 0; nt < 2; nt++) {
            int m = warp * 16 + nt * 8 + g;
            bf[nt][0] = __float_as_uint(Bs[m * BKS + ks * 8 + q]);
            bf[nt][1] = __float_as_uint(Bs[m * BKS + ks * 8 + q + 4]);
        }
        #pragma unroll
        for (int part = 0; part < 2; part++) {
            const float* W = Wh + part * CB * BKS;
            #pragma unroll
            for (int mt = 0; mt < 8; mt++) {
                uint32_t a0 = __float_as_uint(W[(mt * 16 + g    ) * BKS + ks * 8 + q    ]);
                uint32_t a1 = __float_as_uint(W[(mt * 16 + g + 8) * BKS + ks * 8 + q    ]);
                uint32_t a2 = __float_as_uint(W[(mt * 16 + g    ) * BKS + ks * 8 + q + 4]);
                uint32_t a3 = __float_as_uint(W[(mt * 16 + g + 8) * BKS + ks * 8 + q + 4]);
                #pragma unroll
                for (int nt = 0; nt < 2; nt++)
                    mma_tf32(acc[mt][nt], a0, a1, a2, a3, bf[nt][0], bf[nt][1]);
            }
        }
    }

    #pragma unroll
    for (int mt = 0; mt < 8; mt++) {
        float b0 = sb[mt * 16 + g];
        float b1 = sb[mt * 16 + g + 8];
        #pragma unroll
        for (int nt = 0; nt < 2; nt++) {
            int p0 = warp * 16 + nt * 8 + 2 * q;
            #pragma unroll
            for (int c = 0; c < 2; c++) {
                int p = p0 + c;
                float* o = &d_feats[(oy * FEAT + ox0 + p) * CB + mt * 16 + g];
                o[0] = to_tf32(acc[mt][nt][0 + c] + b0);
                o[8] = to_tf32(acc[mt][nt][2 + c] + b1);
            }
        }
    }
}

// ---------------- kernel 3a: fold head weights through the 3x3 conv ----------------
__global__ void fold_w_kernel(const float* __restrict__ Wi,
                              const float* __restrict__ Wc,
                              const float* __restrict__ Wr) {
    __shared__ float wrow[256];
    int r = blockIdx.x;              // 1152 rows
    int t = threadIdx.x;             // 64 threads
    #pragma unroll
    for (int i = 0; i < 4; i++) wrow[t + 64 * i] = Wi[r * 256 + t + 64 * i];
    __syncthreads();
    if (t < NHEAD) {
        float acc = 0.0f;
        if (t < 45) {
            float p0 = 0.f, p1 = 0.f, p2 = 0.f, p3 = 0.f;
            if (t < 9) {
                #pragma unroll 4
                for (int m = 0; m < 256; m += 4) {
                    p0 += wrow[m + 0] * Wc[(m + 0) * 9 + t];
                    p1 += wrow[m + 1] * Wc[(m + 1) * 9 + t];
                    p2 += wrow[m + 2] * Wc[(m + 2) * 9 + t];
                    p3 += wrow[m + 3] * Wc[(m + 3) * 9 + t];
                }
            } else {
                int o = t - 9;
                #pragma unroll 4
                for (int m = 0; m < 256; m += 4) {
                    p0 += wrow[m + 0] * Wr[(m + 0) * 36 + o];
                    p1 += wrow[m + 1] * Wr[(m + 1) * 36 + o];
                    p2 += wrow[m + 2] * Wr[(m + 2) * 36 + o];
                    p3 += wrow[m + 3] * Wr[(m + 3) * 36 + o];
                }
            }
            acc = (p0 + p1) + (p2 + p3);
        }
        d_wf[r * NHEAD + t] = to_tf32(acc);
    }
}

// ---------------- kernel 3b: fold biases ----------------
__global__ void fold_b_kernel(const float* __restrict__ bi,
                              const float* __restrict__ Wc, const float* __restrict__ bc,
                              const float* __restrict__ Wr, const float* __restrict__ br) {
    int t = threadIdx.x;             // 64 threads
    if (t < NHEAD) {
        float acc = 0.0f;
        if (t < 45) {
            if (t < 9) {
                for (int m = 0; m < 256; m++) acc += bi[m] * Wc[m * 9 + t];
                acc += bc[t];
            } else {
                int o = t - 9;
                for (int m = 0; m < 256; m++) acc += bi[m] * Wr[m * 36 + o];
                acc += br[o];
            }
        }
        d_bfold[t] = acc;
    }
}

// ---------------- kernel 4: head conv (tf32 MMA) + fused per-gt IoU max ----------------
// One block per output row u. After the GEMM epilogue the block also computes the
// gt-max IoU contribution of its 254x9 anchors (ALU work overlapping other blocks' MMA).
#define ASTR 20
__global__ __launch_bounds__(256) void head_mma_kernel(const float* __restrict__ gt) {
    __shared__ float As[NHEAD * ASTR];         // weights [o*ASTR + k], k<16
    __shared__ float Bs[256 * ASTR];           // acts [m*ASTR + k]
    __shared__ unsigned int skey[K_GT];
    __shared__ float sgt[K_GT * 4];
    int tid  = threadIdx.x;
    int u    = blockIdx.x;
    int warp = tid >> 5, lane = tid & 31;
    int g = lane >> 2, q = lane & 3;

    if (tid < K_GT)     skey[tid] = 0u;
    if (tid < K_GT * 4) sgt[tid]  = gt[tid];

    float acc[3][4][4];
    #pragma unroll
    for (int mt = 0; mt < 3; mt++)
        #pragma unroll
        for (int nt = 0; nt < 4; nt++)
            #pragma unroll
            for (int i = 0; i < 4; i++) acc[mt][nt][i] = 0.0f;

    for (int kc = 0; kc < 72; kc++) {
        int s  = kc >> 3;                 // 3x3 tap
        int c0 = (kc & 7) << 4;           // channel base within tap (16 per chunk)
        int dy = s / 3, dx = s - dy * 3;
        int base = s * CB + c0;

        __syncthreads();
        #pragma unroll
        for (int j = 0; j < 3; j++) {
            int idx = tid + 256 * j;      // 0..767
            int k = idx / NHEAD, o = idx - (idx / NHEAD) * NHEAD;
            As[o * ASTR + k] = d_wf[(base + k) * NHEAD + o];
        }
        const float* fb = d_feats + (u + dy) * (FEAT * CB);
        #pragma unroll
        for (int j = 0; j < 4; j++) {
            int idx = tid + 256 * j;      // 1024 float4
            int m = idx >> 2, qq = idx & 3;
            int col = m + dx; if (col > 255) col = 255;   // only padded outputs touch clamp
            float4 v = *(const float4*)(fb + col * CB + c0 + qq * 4);
            *(float4*)&Bs[m * ASTR + qq * 4] = v;
        }
        __syncthreads();

        #pragma unroll
        for (int ks = 0; ks < 2; ks++) {
            uint32_t bf[4][2];
            #pragma unroll
            for (int nt = 0; nt < 4; nt++) {
                int m = warp * 32 + nt * 8 + g;
                bf[nt][0] = __float_as_uint(Bs[m * ASTR + ks * 8 + q]);
                bf[nt][1] = __float_as_uint(Bs[m * ASTR + ks * 8 + q + 4]);
            }
            #pragma unroll
            for (int mt = 0; mt < 3; mt++) {
                int ro = mt * 16;
                uint32_t a0 = __float_as_uint(As[(ro + g    ) * ASTR + ks * 8 + q    ]);
                uint32_t a1 = __float_as_uint(As[(ro + g + 8) * ASTR + ks * 8 + q    ]);
                uint32_t a2 = __float_as_uint(As[(ro + g    ) * ASTR + ks * 8 + q + 4]);
                uint32_t a3 = __float_as_uint(As[(ro + g + 8) * ASTR + ks * 8 + q + 4]);
                #pragma unroll
                for (int nt = 0; nt < 4; nt++)
                    mma_tf32(acc[mt][nt], a0, a1, a2, a3, bf[nt][0], bf[nt][1]);
            }
        }
    }

    #pragma unroll
    for (int mt = 0; mt < 3; mt++) {
        float b0 = d_bfold[mt * 16 + g];
        float b1 = d_bfold[mt * 16 + g + 8];
        #pragma unroll
        for (int nt = 0; nt < 4; nt++) {
            int v0 = warp * 32 + nt * 8 + 2 * q;
            #pragma unroll
            for (int c = 0; c < 2; c++) {
                int v = v0 + c;
                if (v < FM) {
                    float* o = d_head + (u * FM + v) * NHEAD + mt * 16 + g;
                    o[0] = acc[mt][nt][0 + c] + b0;
                    o[8] = acc[mt][nt][2 + c] + b1;
                }
            }
        }
    }

    // ---- fused pass1 for this block's x-grid row u ----
    float mg[K_GT];
    #pragma unroll
    for (int g2 = 0; g2 < K_GT; g2++) mg[g2] = -1.0f;
    for (int idx = tid; idx < FM * 9; idx += 256) {
        int v = idx / 9, a = idx - v * 9;
        float x1, y1, x2, y2; bool inside;
        anchor_box(u, v, a, x1, y1, x2, y2, inside);
        if (inside) {
            #pragma unroll
            for (int g2 = 0; g2 < K_GT; g2++) {
                float io = iou_exact(x1, y1, x2, y2,
                                     sgt[g2 * 4 + 0], sgt[g2 * 4 + 1],
                                     sgt[g2 * 4 + 2], sgt[g2 * 4 + 3]);
                mg[g2] = fmaxf(mg[g2], io);
            }
        }
    }
    __syncthreads();
    #pragma unroll
    for (int g2 = 0; g2 < K_GT; g2++) {
        float m = mg[g2];
        #pragma unroll
        for (int off = 16; off > 0; off >>= 1)
            m = fmaxf(m, __shfl_xor_sync(0xffffffffu, m, off));
        if (lane == 0) atomicMax(&skey[g2], fkey(m));
    }
    __syncthreads();
    if (tid < K_GT) atomicMax(&d_gtkey[tid], skey[tid]);
}

// ---------------- kernel 5: labels + losses (2 positions per warp) ----------------
__global__ void loss_kernel(const float* __restrict__ gt) {
    __shared__ float sgt[K_GT * 4];
    __shared__ float sgtmax[K_GT];
    __shared__ double sacc[4];
    int t = threadIdx.x;
    if (t < K_GT * 4) sgt[t] = gt[t];
    if (t < K_GT)     sgtmax[t] = fdecode(d_gtkey[t]);
    if (t < 4)        sacc[t] = 0.0;
    __syncthreads();

    int w = t >> 5, lane = t & 31;
    int half = lane >> 4, sub = lane & 15;
    int p = blockIdx.x * 16 + w * 2 + half;

    float myc = 0.0f, mysel = 0.0f, mybox = 0.0f, mypos = 0.0f;

    if (p < NPOS && sub < 9) {
        const float* hrow = d_head + p * NHEAD;
        float cls_v = hrow[sub];
        float regv[4];
        #pragma unroll
        for (int d = 0; d < 4; d++) regv[d] = hrow[9 + sub * 4 + d];

        int u = p / FM, v = p - u * FM;               // u -> x-grid, v -> y-grid
        float x1, y1, x2, y2; bool inside;
        anchor_box(u, v, sub, x1, y1, x2, y2, inside);

        float maxiou = -1e30f;
        bool best = false;
        #pragma unroll
        for (int g = 0; g < K_GT; g++) {
            float io = iou_exact(x1, y1, x2, y2,
                                 sgt[g * 4 + 0], sgt[g * 4 + 1],
                                 sgt[g * 4 + 2], sgt[g * 4 + 3]);
            if (inside && (io == sgtmax[g])) best = true;
            maxiou = fmaxf(maxiou, io);
        }
        bool pos = inside && (best || (maxiou >= 0.5f));

        if (inside) {
            mysel = 1.0f;
            myc = pos ? softplus_f(-cls_v) : softplus_f(cls_v);
        }
        if (pos) {
            mypos = 1.0f;
            #pragma unroll
            for (int d = 0; d < 4; d++) {
                float ab = fabsf(regv[d]);
                mybox += (ab < 1.0f) ? (0.5f * ab * ab) : (ab - 0.5f);
            }
        }
    }

    #pragma unroll
    for (int off = 16; off > 0; off >>= 1) {
        myc   += __shfl_xor_sync(0xffffffffu, myc,   off);
        mysel += __shfl_xor_sync(0xffffffffu, mysel, off);
        mybox += __shfl_xor_sync(0xffffffffu, mybox, off);
        mypos += __shfl_xor_sync(0xffffffffu, mypos, off);
    }
    if (lane == 0) {
        atomicAdd(&sacc[0], (double)myc);
        atomicAdd(&sacc[1], (double)mysel);
        atomicAdd(&sacc[2], (double)mybox);
        atomicAdd(&sacc[3], (double)mypos);
    }
    __syncthreads();
    if (t < 4) atomicAdd(&d_acc[t], sacc[t]);
}

// ---------------- kernel 6: finalize ----------------
__global__ void fin_kernel(float* out) {
    if (threadIdx.x == 0) {
        double cls = d_acc[0] / d_acc[1];
        double box = d_acc[2] / d_acc[3];
        out[0] = (float)(cls + box);
    }
}

// ---------------- launch ----------------
extern "C" void kernel_launch(void* const* d_in, const int* in_sizes, int n_in,
                              void* d_out, int out_size) {
    const float* image = (const float*)d_in[0];
    const float* gt    = (const float*)d_in[1];
    const float* Wb    = (const float*)d_in[2];
    const float* bb    = (const float*)d_in[3];
    const float* Wi    = (const float*)d_in[4];
    const float* bi    = (const float*)d_in[5];
    const float* Wc    = (const float*)d_in[6];
    const float* bc    = (const float*)d_in[7];
    const float* Wr    = (const float*)d_in[8];
    const float* br    = (const float*)d_in[9];

    const int bsm = (3 * CB * BKS + CB) * sizeof(float);   // 80384 B
    cudaFuncSetAttribute(backbone_mma_kernel,
                         cudaFuncAttributeMaxDynamicSharedMemorySize, bsm);

    init_kernel<<<1, 32>>>();
    wb_prep_kernel<<<24, 256>>>(Wb);
    fold_w_kernel<<<1152, 64>>>(Wi, Wc, Wr);
    fold_b_kernel<<<1, 64>>>(bi, Wc, bc, Wr, br);
    backbone_mma_kernel<<<512, 256, bsm>>>(image, bb);
    head_mma_kernel<<<FM, 256>>>(gt);
    loss_kernel<<<(NPOS + 15) / 16, 256>>>(gt);
    fin_kernel<<<1, 32>>>((float*)d_out);
}